// round 4
// baseline (speedup 1.0000x reference)
#include <cuda_runtime.h>
#include <math.h>
#include <stdint.h>

#define Bz   2
#define Sz   2048
#define Dz   2048
#define Hz   16
#define DHz  128
#define Fz   5504
#define NTz  (Bz*Sz)      // 4096 tokens
#define BHz  (Bz*Hz)      // 32
#define ATTN_SCALE 0.08838834764831845f   // 1/sqrt(128)

// ---------------- scratch (device globals; allocation-free) ----------------
__device__ float g_h1 [(size_t)NTz*Dz];      // rmsnorm1 out, reused as h3
__device__ float g_q  [(size_t)NTz*Dz];
__device__ float g_k  [(size_t)NTz*Dz];
__device__ float g_v  [(size_t)NTz*Dz];
__device__ float g_ctx[(size_t)NTz*Dz];
__device__ float g_h2 [(size_t)NTz*Dz];      // attn residual out
__device__ float g_sc [(size_t)BHz*Sz*Sz];   // 512 MB attention scores/probs
__device__ float g_rs [(size_t)BHz*Sz];      // softmax row sums
__device__ float g_gate[(size_t)NTz*Fz];
__device__ float g_up  [(size_t)NTz*Fz];
__device__ int   g_choice[NTz];

// ---------------- rmsnorm ----------------
__global__ __launch_bounds__(256) void rmsnorm_kernel(
    const float* __restrict__ x, const float* __restrict__ w, float* __restrict__ out)
{
    const int row = blockIdx.x;
    const float* xr = x + (size_t)row * Dz;
    float* orow = out + (size_t)row * Dz;
    const int tid = threadIdx.x;
    float ss = 0.f;
    #pragma unroll
    for (int i = tid*4; i < Dz; i += 1024) {
        float4 v = *(const float4*)(xr + i);
        ss += v.x*v.x + v.y*v.y + v.z*v.z + v.w*v.w;
    }
    __shared__ float red[256];
    red[tid] = ss; __syncthreads();
    for (int s = 128; s > 0; s >>= 1) { if (tid < s) red[tid] += red[tid+s]; __syncthreads(); }
    const float scale = rsqrtf(red[0] / (float)Dz + 1e-6f);
    #pragma unroll
    for (int i = tid*4; i < Dz; i += 1024) {
        float4 v = *(const float4*)(xr + i);
        float4 ww = *(const float4*)(w + i);
        float4 o;
        o.x = v.x*scale*ww.x; o.y = v.y*scale*ww.y;
        o.z = v.z*scale*ww.z; o.w = v.w*scale*ww.w;
        *(float4*)(orow + i) = o;
    }
}

// ---------------- generic SGEMM (NT): C[M,N] = A[M,K] * B[N,K]^T (+bias)(+add) ----------------
// Requires M%128==0, N%128==0, K%16==0 (true for all call sites).
__global__ __launch_bounds__(256) void sgemm_nt(
    const float* __restrict__ A, const float* __restrict__ B,
    float* __restrict__ C, const float* __restrict__ bias,
    const float* __restrict__ add, int M, int N, int K)
{
    __shared__ float As[16][132];
    __shared__ float Bs[16][132];
    const int tid = threadIdx.x;
    const int bm = blockIdx.y, bn = blockIdx.x;
    const int r  = tid >> 1;
    const int kc = (tid & 1) * 8;
    const float* Ab = A + (size_t)(bm*128 + r) * K;
    const float* Bb = B + (size_t)(bn*128 + r) * K;
    const int tm = (tid >> 4) * 8;
    const int tn = (tid & 15) * 8;
    float acc[8][8];
    #pragma unroll
    for (int i = 0; i < 8; i++)
        #pragma unroll
        for (int j = 0; j < 8; j++) acc[i][j] = 0.f;

    for (int k0 = 0; k0 < K; k0 += 16) {
        float4 a0 = *(const float4*)(Ab + k0 + kc);
        float4 a1 = *(const float4*)(Ab + k0 + kc + 4);
        float4 b0 = *(const float4*)(Bb + k0 + kc);
        float4 b1 = *(const float4*)(Bb + k0 + kc + 4);
        As[kc+0][r]=a0.x; As[kc+1][r]=a0.y; As[kc+2][r]=a0.z; As[kc+3][r]=a0.w;
        As[kc+4][r]=a1.x; As[kc+5][r]=a1.y; As[kc+6][r]=a1.z; As[kc+7][r]=a1.w;
        Bs[kc+0][r]=b0.x; Bs[kc+1][r]=b0.y; Bs[kc+2][r]=b0.z; Bs[kc+3][r]=b0.w;
        Bs[kc+4][r]=b1.x; Bs[kc+5][r]=b1.y; Bs[kc+6][r]=b1.z; Bs[kc+7][r]=b1.w;
        __syncthreads();
        #pragma unroll
        for (int kk = 0; kk < 16; kk++) {
            float ar[8], br[8];
            #pragma unroll
            for (int i = 0; i < 8; i++) ar[i] = As[kk][tm+i];
            #pragma unroll
            for (int j = 0; j < 8; j++) br[j] = Bs[kk][tn+j];
            #pragma unroll
            for (int i = 0; i < 8; i++)
                #pragma unroll
                for (int j = 0; j < 8; j++)
                    acc[i][j] = fmaf(ar[i], br[j], acc[i][j]);
        }
        __syncthreads();
    }
    const size_t row0 = (size_t)bm*128 + tm;
    const int    col0 = bn*128 + tn;
    #pragma unroll
    for (int i = 0; i < 8; i++) {
        size_t off = (row0 + i) * (size_t)N + col0;
        #pragma unroll
        for (int j = 0; j < 8; j++) {
            float vv = acc[i][j];
            if (bias) vv += bias[col0 + j];
            if (add)  vv += add[off + j];
            C[off + j] = vv;
        }
    }
}

// ---------------- RoPE (in-place on q and k) ----------------
__global__ __launch_bounds__(256) void rope_kernel(float* __restrict__ q, float* __restrict__ k)
{
    const size_t idx = (size_t)blockIdx.x * 256 + threadIdx.x;   // NTz*Hz*64 threads
    if (idx >= (size_t)NTz * Hz * 64) return;
    const int    j    = (int)(idx & 63);
    const size_t th   = idx >> 6;
    const int    head = (int)(th & 15);
    const size_t tok  = th >> 4;
    const int    s    = (int)(tok & (Sz - 1));
    // angle in double for phase accuracy at large s
    const double inv  = exp(-(double)(2*j) / 128.0 * 9.210340371976184); // ln(10000)
    const double ang  = (double)s * inv;
    const float  c  = (float)cos(ang);
    const float  sn = (float)sin(ang);
    const size_t base = tok * (size_t)Dz + (size_t)head * DHz + j;
    float q1 = q[base], q2 = q[base + 64];
    q[base]      = q1*c - q2*sn;
    q[base + 64] = q2*c + q1*sn;
    float k1 = k[base], k2 = k[base + 64];
    k[base]      = k1*c - k2*sn;
    k[base + 64] = k2*c + k1*sn;
}

// ---------------- attention scores: Sc[bh] = Q Kt / sqrt(DH), causal ----------------
__global__ __launch_bounds__(256) void attn_scores(
    const float* __restrict__ Q, const float* __restrict__ Km, float* __restrict__ Sc)
{
    const int z = blockIdx.z, b = z >> 4, h = z & 15;
    const int bm = blockIdx.y, bn = blockIdx.x;
    const int tid = threadIdx.x;
    const int tm = (tid >> 4) * 8;
    const int tn = (tid & 15) * 8;
    float* Cb = Sc + (size_t)z * Sz * Sz;
    const size_t row0 = (size_t)bm*128 + tm;
    const int    col0 = bn*128 + tn;

    if (bn > bm) {  // fully masked block: just write -inf surrogate
        #pragma unroll
        for (int i = 0; i < 8; i++) {
            size_t off = (row0 + i) * (size_t)Sz + col0;
            #pragma unroll
            for (int j = 0; j < 8; j++) Cb[off + j] = -1e30f;
        }
        return;
    }

    __shared__ float As[16][132];
    __shared__ float Bs[16][132];
    const int r  = tid >> 1;
    const int kc = (tid & 1) * 8;
    const float* Qb = Q  + ((size_t)(b*Sz + bm*128 + r)) * Dz + (size_t)h * DHz;
    const float* Kb = Km + ((size_t)(b*Sz + bn*128 + r)) * Dz + (size_t)h * DHz;
    float acc[8][8];
    #pragma unroll
    for (int i = 0; i < 8; i++)
        #pragma unroll
        for (int j = 0; j < 8; j++) acc[i][j] = 0.f;

    for (int k0 = 0; k0 < DHz; k0 += 16) {
        float4 a0 = *(const float4*)(Qb + k0 + kc);
        float4 a1 = *(const float4*)(Qb + k0 + kc + 4);
        float4 b0 = *(const float4*)(Kb + k0 + kc);
        float4 b1 = *(const float4*)(Kb + k0 + kc + 4);
        As[kc+0][r]=a0.x; As[kc+1][r]=a0.y; As[kc+2][r]=a0.z; As[kc+3][r]=a0.w;
        As[kc+4][r]=a1.x; As[kc+5][r]=a1.y; As[kc+6][r]=a1.z; As[kc+7][r]=a1.w;
        Bs[kc+0][r]=b0.x; Bs[kc+1][r]=b0.y; Bs[kc+2][r]=b0.z; Bs[kc+3][r]=b0.w;
        Bs[kc+4][r]=b1.x; Bs[kc+5][r]=b1.y; Bs[kc+6][r]=b1.z; Bs[kc+7][r]=b1.w;
        __syncthreads();
        #pragma unroll
        for (int kk = 0; kk < 16; kk++) {
            float ar[8], br[8];
            #pragma unroll
            for (int i = 0; i < 8; i++) ar[i] = As[kk][tm+i];
            #pragma unroll
            for (int j = 0; j < 8; j++) br[j] = Bs[kk][tn+j];
            #pragma unroll
            for (int i = 0; i < 8; i++)
                #pragma unroll
                for (int j = 0; j < 8; j++)
                    acc[i][j] = fmaf(ar[i], br[j], acc[i][j]);
        }
        __syncthreads();
    }
    #pragma unroll
    for (int i = 0; i < 8; i++) {
        const int qrow = bm*128 + tm + i;
        size_t off = (row0 + i) * (size_t)Sz + col0;
        #pragma unroll
        for (int j = 0; j < 8; j++) {
            const int kcol = col0 + j;
            Cb[off + j] = (kcol <= qrow) ? acc[i][j] * ATTN_SCALE : -1e30f;
        }
    }
}

// ---------------- softmax rows (writes exp(x-max), rowsum separately) ----------------
__global__ __launch_bounds__(256) void softmax_kernel(float* __restrict__ Sc, float* __restrict__ rowsum)
{
    const size_t row = blockIdx.x;
    float* p = Sc + row * (size_t)Sz;
    const int tid = threadIdx.x;
    float m = -1e30f;
    #pragma unroll
    for (int i = tid*4; i < Sz; i += 1024) {
        float4 v = *(const float4*)(p + i);
        m = fmaxf(m, fmaxf(fmaxf(v.x, v.y), fmaxf(v.z, v.w)));
    }
    __shared__ float red[256];
    red[tid] = m; __syncthreads();
    for (int s = 128; s > 0; s >>= 1) { if (tid < s) red[tid] = fmaxf(red[tid], red[tid+s]); __syncthreads(); }
    m = red[0];
    __syncthreads();
    float sum = 0.f;
    #pragma unroll
    for (int i = tid*4; i < Sz; i += 1024) {
        float4 v = *(const float4*)(p + i);
        v.x = expf(v.x - m); v.y = expf(v.y - m);
        v.z = expf(v.z - m); v.w = expf(v.w - m);
        sum += v.x + v.y + v.z + v.w;
        *(float4*)(p + i) = v;
    }
    red[tid] = sum; __syncthreads();
    for (int s = 128; s > 0; s >>= 1) { if (tid < s) red[tid] += red[tid+s]; __syncthreads(); }
    if (tid == 0) rowsum[row] = red[0];
}

// ---------------- attention ctx: Cx[bh] = P V (NN), normalized by rowsum ----------------
__global__ __launch_bounds__(256) void attn_ctx(
    const float* __restrict__ P, const float* __restrict__ V,
    const float* __restrict__ rowsum, float* __restrict__ Cx)
{
    const int z = blockIdx.z, b = z >> 4, h = z & 15;
    const int bm = blockIdx.y;
    const int tid = threadIdx.x;
    const float* Pb = P + (size_t)z * Sz * Sz + (size_t)(bm*128) * Sz;
    const float* Vb = V + (size_t)(b*Sz) * Dz + (size_t)h * DHz;
    float* Cb = Cx + (size_t)(b*Sz + bm*128) * Dz + (size_t)h * DHz;

    __shared__ float As[16][132];
    __shared__ float Bs[16][132];
    const int rA  = tid >> 1;            // P loader: row of 128-row tile
    const int kcA = (tid & 1) * 8;
    const int rB  = tid >> 4;            // V loader: k-row of 16-row tile
    const int ncB = (tid & 15) * 8;
    const int tm = (tid >> 4) * 8;
    const int tn = (tid & 15) * 8;
    float acc[8][8];
    #pragma unroll
    for (int i = 0; i < 8; i++)
        #pragma unroll
        for (int j = 0; j < 8; j++) acc[i][j] = 0.f;

    const int Kend = (bm + 1) * 128;   // causal: P is exactly 0 beyond this
    for (int k0 = 0; k0 < Kend; k0 += 16) {
        float4 a0 = *(const float4*)(Pb + (size_t)rA * Sz + k0 + kcA);
        float4 a1 = *(const float4*)(Pb + (size_t)rA * Sz + k0 + kcA + 4);
        As[kcA+0][rA]=a0.x; As[kcA+1][rA]=a0.y; As[kcA+2][rA]=a0.z; As[kcA+3][rA]=a0.w;
        As[kcA+4][rA]=a1.x; As[kcA+5][rA]=a1.y; As[kcA+6][rA]=a1.z; As[kcA+7][rA]=a1.w;
        float4 b0 = *(const float4*)(Vb + (size_t)(k0 + rB) * Dz + ncB);
        float4 b1 = *(const float4*)(Vb + (size_t)(k0 + rB) * Dz + ncB + 4);
        *(float4*)&Bs[rB][ncB]     = b0;
        *(float4*)&Bs[rB][ncB + 4] = b1;
        __syncthreads();
        #pragma unroll
        for (int kk = 0; kk < 16; kk++) {
            float ar[8], br[8];
            #pragma unroll
            for (int i = 0; i < 8; i++) ar[i] = As[kk][tm+i];
            #pragma unroll
            for (int j = 0; j < 8; j++) br[j] = Bs[kk][tn+j];
            #pragma unroll
            for (int i = 0; i < 8; i++)
                #pragma unroll
                for (int j = 0; j < 8; j++)
                    acc[i][j] = fmaf(ar[i], br[j], acc[i][j]);
        }
        __syncthreads();
    }
    #pragma unroll
    for (int i = 0; i < 8; i++) {
        const float inv = 1.f / rowsum[(size_t)z * Sz + bm*128 + tm + i];
        #pragma unroll
        for (int j = 0; j < 8; j++)
            Cb[(size_t)(tm + i) * Dz + tn + j] = acc[i][j] * inv;
    }
}

// ---------------- router: top-1 of 2 experts ----------------
__global__ __launch_bounds__(256) void router_kernel(
    const float* __restrict__ h, const float* __restrict__ rw,
    const float* __restrict__ rb, int* __restrict__ choice)
{
    const int t = blockIdx.x;
    const float* xr = h + (size_t)t * Dz;
    const int tid = threadIdx.x;
    float s0 = 0.f, s1 = 0.f;
    #pragma unroll
    for (int i = tid*4; i < Dz; i += 1024) {
        float4 v  = *(const float4*)(xr + i);
        float4 w0 = *(const float4*)(rw + i);
        float4 w1 = *(const float4*)(rw + Dz + i);
        s0 += v.x*w0.x + v.y*w0.y + v.z*w0.z + v.w*w0.w;
        s1 += v.x*w1.x + v.y*w1.y + v.z*w1.z + v.w*w1.w;
    }
    __shared__ float r0[256], r1[256];
    r0[tid] = s0; r1[tid] = s1; __syncthreads();
    for (int s = 128; s > 0; s >>= 1) {
        if (tid < s) { r0[tid] += r0[tid+s]; r1[tid] += r1[tid+s]; }
        __syncthreads();
    }
    if (tid == 0) {
        const float l0 = r0[0] + rb[0], l1 = r1[0] + rb[1];
        choice[t] = (l1 > l0) ? 1 : 0;   // argmax, first index wins on tie
    }
}

// ---------------- act = silu(gate)*up * (choice==e), in-place into gate ----------------
__global__ __launch_bounds__(256) void act_kernel(
    float* __restrict__ gate, const float* __restrict__ up,
    const int* __restrict__ choice, int e)
{
    const int f = blockIdx.x * 256 + threadIdx.x;
    if (f >= Fz) return;
    const int tok = blockIdx.y;
    const size_t idx = (size_t)tok * Fz + f;
    if (choice[tok] == e) {
        const float g = gate[idx];
        gate[idx] = (g / (1.f + expf(-g))) * up[idx];
    } else {
        gate[idx] = 0.f;
    }
}

// ---------------- launch ----------------
extern "C" void kernel_launch(void* const* d_in, const int* in_sizes, int n_in,
                              void* d_out, int out_size)
{
    const float* x    = (const float*)d_in[0];
    const float* ln1w = (const float*)d_in[1];
    const float* wq   = (const float*)d_in[2];
    const float* bq   = (const float*)d_in[3];
    const float* wk   = (const float*)d_in[4];
    const float* bk   = (const float*)d_in[5];
    const float* wv   = (const float*)d_in[6];
    const float* bv   = (const float*)d_in[7];
    const float* wo   = (const float*)d_in[8];
    const float* ln2w = (const float*)d_in[9];
    const float* e1g  = (const float*)d_in[10];
    const float* e1u  = (const float*)d_in[11];
    const float* e1d  = (const float*)d_in[12];
    const float* e2g  = (const float*)d_in[13];
    const float* e2u  = (const float*)d_in[14];
    const float* e2d  = (const float*)d_in[15];
    const float* rw   = (const float*)d_in[16];
    const float* rb   = (const float*)d_in[17];
    float* out = (float*)d_out;

    float *h1, *q, *k, *v, *ctx, *h2, *sc, *rs, *gate, *up;
    int* choice;
    cudaGetSymbolAddress((void**)&h1,  g_h1);
    cudaGetSymbolAddress((void**)&q,   g_q);
    cudaGetSymbolAddress((void**)&k,   g_k);
    cudaGetSymbolAddress((void**)&v,   g_v);
    cudaGetSymbolAddress((void**)&ctx, g_ctx);
    cudaGetSymbolAddress((void**)&h2,  g_h2);
    cudaGetSymbolAddress((void**)&sc,  g_sc);
    cudaGetSymbolAddress((void**)&rs,  g_rs);
    cudaGetSymbolAddress((void**)&gate, g_gate);
    cudaGetSymbolAddress((void**)&up,   g_up);
    cudaGetSymbolAddress((void**)&choice, g_choice);

    // --- attention block ---
    rmsnorm_kernel<<<NTz, 256>>>(x, ln1w, h1);
    sgemm_nt<<<dim3(Dz/128, NTz/128), 256>>>(h1, wq, q, bq, nullptr, NTz, Dz, Dz);
    sgemm_nt<<<dim3(Dz/128, NTz/128), 256>>>(h1, wk, k, bk, nullptr, NTz, Dz, Dz);
    sgemm_nt<<<dim3(Dz/128, NTz/128), 256>>>(h1, wv, v, bv, nullptr, NTz, Dz, Dz);
    rope_kernel<<<(NTz*Hz*64)/256, 256>>>(q, k);
    attn_scores<<<dim3(Sz/128, Sz/128, BHz), 256>>>(q, k, sc);
    softmax_kernel<<<BHz*Sz, 256>>>(sc, rs);
    attn_ctx<<<dim3(1, Sz/128, BHz), 256>>>(sc, v, rs, ctx);
    sgemm_nt<<<dim3(Dz/128, NTz/128), 256>>>(ctx, wo, h2, nullptr, x, NTz, Dz, Dz);

    // --- MoE block ---
    rmsnorm_kernel<<<NTz, 256>>>(h2, ln2w, h1);          // h1 = h3
    router_kernel<<<NTz, 256>>>(h1, rw, rb, choice);

    // expert 1 (choice==0): out = h2 + act1 @ d1^T
    sgemm_nt<<<dim3(Fz/128, NTz/128), 256>>>(h1, e1g, gate, nullptr, nullptr, NTz, Fz, Dz);
    sgemm_nt<<<dim3(Fz/128, NTz/128), 256>>>(h1, e1u, up,   nullptr, nullptr, NTz, Fz, Dz);
    act_kernel<<<dim3((Fz+255)/256, NTz), 256>>>(gate, up, choice, 0);
    sgemm_nt<<<dim3(Dz/128, NTz/128), 256>>>(gate, e1d, out, nullptr, h2, NTz, Dz, Fz);

    // expert 2 (choice==1): out += act2 @ d2^T  (in-place add)
    sgemm_nt<<<dim3(Fz/128, NTz/128), 256>>>(h1, e2g, gate, nullptr, nullptr, NTz, Fz, Dz);
    sgemm_nt<<<dim3(Fz/128, NTz/128), 256>>>(h1, e2u, up,   nullptr, nullptr, NTz, Fz, Dz);
    act_kernel<<<dim3((Fz+255)/256, NTz), 256>>>(gate, up, choice, 1);
    sgemm_nt<<<dim3(Dz/128, NTz/128), 256>>>(gate, e2d, out, nullptr, out, NTz, Dz, Fz);
}

// round 5
// speedup vs baseline: 2.5123x; 2.5123x over previous
#include <cuda_runtime.h>
#include <math.h>
#include <stdint.h>

#define Bz   2
#define Sz   2048
#define Dz   2048
#define Hz   16
#define DHz  128
#define Fz   5504
#define NTz  (Bz*Sz)      // 4096 tokens
#define BHz  (Bz*Hz)      // 32
#define ATTN_SCALE 0.08838834764831845f   // 1/sqrt(128)

// ---------------- scratch (device globals; allocation-free) ----------------
__device__ float g_h1 [(size_t)NTz*Dz];
__device__ float g_q  [(size_t)NTz*Dz];
__device__ float g_k  [(size_t)NTz*Dz];
__device__ float g_v  [(size_t)NTz*Dz];
__device__ float g_ctx[(size_t)NTz*Dz];
__device__ float g_h2 [(size_t)NTz*Dz];
__device__ float g_sc [(size_t)BHz*Sz*Sz];   // 512 MB scores/probs
__device__ float g_rs [(size_t)BHz*Sz];
__device__ float g_gate[(size_t)NTz*Fz];
__device__ float g_up  [(size_t)NTz*Fz];
__device__ int   g_choice[NTz];

// ================= TF32 MMA machinery =================
// Block tile 128x128x32, 256 threads (8 warps), warp tile 32(M)x64(N).
// Smem: A,B stored [row][k] pitch 36 floats (conflict-free for mma frag LDS).
// ctx variant: B stored [k][n] pitch 132.

#define PITCH  36
#define PITCHC 132
#define A_FLOATS (128*PITCH)           // 4608
#define STAGE_NT (2*A_FLOATS)          // A + B per stage
#define STAGE_CTX (A_FLOATS + 32*PITCHC)

__device__ __forceinline__ unsigned sptr(const void* p){ return (unsigned)__cvta_generic_to_shared(p); }
__device__ __forceinline__ void cpa16(unsigned s, const float* g){
    asm volatile("cp.async.cg.shared.global [%0], [%1], 16;\n" :: "r"(s), "l"(g));
}
__device__ __forceinline__ void cpcommit(){ asm volatile("cp.async.commit_group;\n" ::); }
__device__ __forceinline__ void cpwait1(){ asm volatile("cp.async.wait_group 1;\n" ::); }
__device__ __forceinline__ unsigned f2tf(float f){
    unsigned u; asm("cvt.rna.tf32.f32 %0, %1;" : "=r"(u) : "f"(f)); return u;
}
__device__ __forceinline__ void mma8(float* c, unsigned a0,unsigned a1,unsigned a2,unsigned a3,
                                     unsigned b0, unsigned b1){
    asm volatile("mma.sync.aligned.m16n8k8.row.col.f32.tf32.tf32.f32 "
                 "{%0,%1,%2,%3},{%4,%5,%6,%7},{%8,%9},{%0,%1,%2,%3};\n"
                 : "+f"(c[0]),"+f"(c[1]),"+f"(c[2]),"+f"(c[3])
                 : "r"(a0),"r"(a1),"r"(a2),"r"(a3),"r"(b0),"r"(b1));
}

// load 128 rows x 32 k-cols into smem [row][k] pitch 36
__device__ __forceinline__ void load_tile_rowk(float* S, const float* G, int ld, int tid){
    const int r = tid >> 1, cb = (tid & 1) * 4;
    const float* g = G + (size_t)r * ld + cb;
    unsigned s = sptr(S) + (unsigned)(r * PITCH + cb) * 4u;
    #pragma unroll
    for (int it = 0; it < 4; it++) cpa16(s + it * 32u, g + it * 8);
}

// load 32 k-rows x 128 n-cols into smem [k][n] pitch 132 (for ctx B = V)
__device__ __forceinline__ void load_tile_kn(float* S, const float* G, int ld, int tid){
    const int r = tid >> 3, cb = (tid & 7) * 16;
    const float* g = G + (size_t)r * ld + cb;
    unsigned s = sptr(S) + (unsigned)(r * PITCHC + cb) * 4u;
    #pragma unroll
    for (int it = 0; it < 4; it++) cpa16(s + it * 16u, g + it * 4);
}

__device__ __forceinline__ void compute_nt(const float* __restrict__ As, const float* __restrict__ Bs,
                                           float acc[2][8][4], int warpM, int warpN, int lane){
    const int gi = lane >> 2, tg = lane & 3;
    #pragma unroll
    for (int kk = 0; kk < 32; kk += 8){
        unsigned a[2][4];
        #pragma unroll
        for (int i = 0; i < 2; i++){
            const int row = warpM*32 + i*16 + gi;
            a[i][0] = f2tf(As[row*PITCH     + kk + tg]);
            a[i][1] = f2tf(As[(row+8)*PITCH + kk + tg]);
            a[i][2] = f2tf(As[row*PITCH     + kk + 4 + tg]);
            a[i][3] = f2tf(As[(row+8)*PITCH + kk + 4 + tg]);
        }
        unsigned b[8][2];
        #pragma unroll
        for (int j = 0; j < 8; j++){
            const int n = warpN*64 + j*8 + gi;
            b[j][0] = f2tf(Bs[n*PITCH + kk + tg]);
            b[j][1] = f2tf(Bs[n*PITCH + kk + 4 + tg]);
        }
        #pragma unroll
        for (int i = 0; i < 2; i++)
            #pragma unroll
            for (int j = 0; j < 8; j++)
                mma8(acc[i][j], a[i][0],a[i][1],a[i][2],a[i][3], b[j][0],b[j][1]);
    }
}

__device__ __forceinline__ void compute_ctx(const float* __restrict__ As, const float* __restrict__ Bs,
                                            float acc[2][8][4], int warpM, int warpN, int lane){
    const int gi = lane >> 2, tg = lane & 3;
    #pragma unroll
    for (int kk = 0; kk < 32; kk += 8){
        unsigned a[2][4];
        #pragma unroll
        for (int i = 0; i < 2; i++){
            const int row = warpM*32 + i*16 + gi;
            a[i][0] = f2tf(As[row*PITCH     + kk + tg]);
            a[i][1] = f2tf(As[(row+8)*PITCH + kk + tg]);
            a[i][2] = f2tf(As[row*PITCH     + kk + 4 + tg]);
            a[i][3] = f2tf(As[(row+8)*PITCH + kk + 4 + tg]);
        }
        unsigned b[8][2];
        #pragma unroll
        for (int j = 0; j < 8; j++){
            const int n = warpN*64 + j*8 + gi;
            b[j][0] = f2tf(Bs[(kk + tg)*PITCHC     + n]);
            b[j][1] = f2tf(Bs[(kk + 4 + tg)*PITCHC + n]);
        }
        #pragma unroll
        for (int i = 0; i < 2; i++)
            #pragma unroll
            for (int j = 0; j < 8; j++)
                mma8(acc[i][j], a[i][0],a[i][1],a[i][2],a[i][3], b[j][0],b[j][1]);
    }
}

// ---------- generic NT: C[M,N] = A[M,K] * B[N,K]^T (+bias)(+add) ----------
extern __shared__ float smem[];
__global__ __launch_bounds__(256, 2) void tf32_gemm_nt(
    const float* __restrict__ A, const float* __restrict__ B,
    float* __restrict__ C, const float* __restrict__ bias,
    const float* __restrict__ add, int M, int N, int K)
{
    const int tid = threadIdx.x, lane = tid & 31, warp = tid >> 5;
    const int warpM = warp & 3, warpN = warp >> 2;
    const int bm = blockIdx.y, bn = blockIdx.x;
    const float* Ag = A + (size_t)bm * 128 * K;
    const float* Bg = B + (size_t)bn * 128 * K;
    float acc[2][8][4];
    #pragma unroll
    for (int i=0;i<2;i++) for (int j=0;j<8;j++) for (int c=0;c<4;c++) acc[i][j][c]=0.f;

    const int T = K / 32;
    load_tile_rowk(smem, Ag, K, tid);
    load_tile_rowk(smem + A_FLOATS, Bg, K, tid);
    cpcommit();
    if (T > 1){
        load_tile_rowk(smem + STAGE_NT, Ag + 32, K, tid);
        load_tile_rowk(smem + STAGE_NT + A_FLOATS, Bg + 32, K, tid);
    }
    cpcommit();
    for (int t = 0; t < T; t++){
        cpwait1(); __syncthreads();
        const float* Sa = smem + (t & 1) * STAGE_NT;
        compute_nt(Sa, Sa + A_FLOATS, acc, warpM, warpN, lane);
        __syncthreads();
        if (t + 2 < T){
            float* Sd = smem + (t & 1) * STAGE_NT;
            load_tile_rowk(Sd, Ag + (t+2)*32, K, tid);
            load_tile_rowk(Sd + A_FLOATS, Bg + (t+2)*32, K, tid);
        }
        cpcommit();
    }
    const int gi = lane >> 2, tg = lane & 3;
    #pragma unroll
    for (int i = 0; i < 2; i++){
        const int row = bm*128 + warpM*32 + i*16 + gi;
        #pragma unroll
        for (int j = 0; j < 8; j++){
            const int col = bn*128 + warpN*64 + j*8 + tg*2;
            float2 v0 = make_float2(acc[i][j][0], acc[i][j][1]);
            float2 v1 = make_float2(acc[i][j][2], acc[i][j][3]);
            if (bias){
                const float b0 = bias[col], b1 = bias[col+1];
                v0.x += b0; v0.y += b1; v1.x += b0; v1.y += b1;
            }
            if (add){
                float2 r0 = *(const float2*)&add[(size_t)row * N + col];
                float2 r1 = *(const float2*)&add[(size_t)(row+8) * N + col];
                v0.x += r0.x; v0.y += r0.y; v1.x += r1.x; v1.y += r1.y;
            }
            *(float2*)&C[(size_t)row * N + col]     = v0;
            *(float2*)&C[(size_t)(row+8) * N + col] = v1;
        }
    }
}

// ---------- attention scores: causal, scaled ----------
__global__ __launch_bounds__(256, 2) void tf32_scores(
    const float* __restrict__ Q, const float* __restrict__ Km, float* __restrict__ Sc)
{
    const int z = blockIdx.z, b = z >> 4, h = z & 15;
    const int bm = blockIdx.y, bn = blockIdx.x;
    const int tid = threadIdx.x;
    float* Cb = Sc + (size_t)z * Sz * Sz;

    if (bn > bm){   // fully masked: fill with -inf surrogate
        const float4 m4 = make_float4(-1e30f,-1e30f,-1e30f,-1e30f);
        #pragma unroll
        for (int it = 0; it < 16; it++){
            const int idx = it * 256 + tid;            // 4096 float4s
            const int r = idx >> 5, c = (idx & 31) * 4;
            *(float4*)&Cb[(size_t)(bm*128 + r) * Sz + bn*128 + c] = m4;
        }
        return;
    }
    const int lane = tid & 31, warp = tid >> 5;
    const int warpM = warp & 3, warpN = warp >> 2;
    const float* Ag = Q  + (size_t)(b*Sz + bm*128) * Dz + (size_t)h * DHz;
    const float* Bg = Km + (size_t)(b*Sz + bn*128) * Dz + (size_t)h * DHz;
    float acc[2][8][4];
    #pragma unroll
    for (int i=0;i<2;i++) for (int j=0;j<8;j++) for (int c=0;c<4;c++) acc[i][j][c]=0.f;

    const int T = DHz / 32;  // 4
    load_tile_rowk(smem, Ag, Dz, tid);
    load_tile_rowk(smem + A_FLOATS, Bg, Dz, tid);
    cpcommit();
    load_tile_rowk(smem + STAGE_NT, Ag + 32, Dz, tid);
    load_tile_rowk(smem + STAGE_NT + A_FLOATS, Bg + 32, Dz, tid);
    cpcommit();
    for (int t = 0; t < T; t++){
        cpwait1(); __syncthreads();
        const float* Sa = smem + (t & 1) * STAGE_NT;
        compute_nt(Sa, Sa + A_FLOATS, acc, warpM, warpN, lane);
        __syncthreads();
        if (t + 2 < T){
            float* Sd = smem + (t & 1) * STAGE_NT;
            load_tile_rowk(Sd, Ag + (t+2)*32, Dz, tid);
            load_tile_rowk(Sd + A_FLOATS, Bg + (t+2)*32, Dz, tid);
        }
        cpcommit();
    }
    const int gi = lane >> 2, tg = lane & 3;
    #pragma unroll
    for (int i = 0; i < 2; i++){
        const int row0 = bm*128 + warpM*32 + i*16 + gi;
        #pragma unroll
        for (int j = 0; j < 8; j++){
            const int col = bn*128 + warpN*64 + j*8 + tg*2;
            float2 v0, v1;
            v0.x = (col   <= row0  ) ? acc[i][j][0]*ATTN_SCALE : -1e30f;
            v0.y = (col+1 <= row0  ) ? acc[i][j][1]*ATTN_SCALE : -1e30f;
            v1.x = (col   <= row0+8) ? acc[i][j][2]*ATTN_SCALE : -1e30f;
            v1.y = (col+1 <= row0+8) ? acc[i][j][3]*ATTN_SCALE : -1e30f;
            *(float2*)&Cb[(size_t)row0 * Sz + col]     = v0;
            *(float2*)&Cb[(size_t)(row0+8) * Sz + col] = v1;
        }
    }
}

// ---------- attention ctx: Cx = P V, causal K-trim, rowsum-normalized ----------
__global__ __launch_bounds__(256, 2) void tf32_ctx(
    const float* __restrict__ P, const float* __restrict__ V,
    const float* __restrict__ rowsum, float* __restrict__ Cx)
{
    const int z = blockIdx.z, b = z >> 4, h = z & 15;
    const int bm = blockIdx.y;
    const int tid = threadIdx.x, lane = tid & 31, warp = tid >> 5;
    const int warpM = warp & 3, warpN = warp >> 2;
    const float* Ag = P + (size_t)z * Sz * Sz + (size_t)bm * 128 * Sz;  // pitch Sz
    const float* Bg = V + (size_t)b * Sz * Dz + (size_t)h * DHz;        // [keypos][DHz] pitch Dz
    float acc[2][8][4];
    #pragma unroll
    for (int i=0;i<2;i++) for (int j=0;j<8;j++) for (int c=0;c<4;c++) acc[i][j][c]=0.f;

    const int T = (bm + 1) * 4;   // K = (bm+1)*128
    load_tile_rowk(smem, Ag, Sz, tid);
    load_tile_kn(smem + A_FLOATS, Bg, Dz, tid);
    cpcommit();
    if (T > 1){
        load_tile_rowk(smem + STAGE_CTX, Ag + 32, Sz, tid);
        load_tile_kn(smem + STAGE_CTX + A_FLOATS, Bg + (size_t)32 * Dz, Dz, tid);
    }
    cpcommit();
    for (int t = 0; t < T; t++){
        cpwait1(); __syncthreads();
        const float* Sa = smem + (t & 1) * STAGE_CTX;
        compute_ctx(Sa, Sa + A_FLOATS, acc, warpM, warpN, lane);
        __syncthreads();
        if (t + 2 < T){
            float* Sd = smem + (t & 1) * STAGE_CTX;
            load_tile_rowk(Sd, Ag + (t+2)*32, Sz, tid);
            load_tile_kn(Sd + A_FLOATS, Bg + (size_t)(t+2) * 32 * Dz, Dz, tid);
        }
        cpcommit();
    }
    const int gi = lane >> 2, tg = lane & 3;
    #pragma unroll
    for (int i = 0; i < 2; i++){
        const int rloc = bm*128 + warpM*32 + i*16 + gi;
        const float inv0 = 1.f / rowsum[(size_t)z * Sz + rloc];
        const float inv1 = 1.f / rowsum[(size_t)z * Sz + rloc + 8];
        const size_t row0 = (size_t)(b*Sz) + rloc;
        #pragma unroll
        for (int j = 0; j < 8; j++){
            const int col = h*DHz + warpN*64 + j*8 + tg*2;
            float2 v0 = make_float2(acc[i][j][0]*inv0, acc[i][j][1]*inv0);
            float2 v1 = make_float2(acc[i][j][2]*inv1, acc[i][j][3]*inv1);
            *(float2*)&Cx[row0 * Dz + col]       = v0;
            *(float2*)&Cx[(row0+8) * Dz + col]   = v1;
        }
    }
}

// ================= elementwise kernels (unchanged) =================
__global__ __launch_bounds__(256) void rmsnorm_kernel(
    const float* __restrict__ x, const float* __restrict__ w, float* __restrict__ out)
{
    const int row = blockIdx.x;
    const float* xr = x + (size_t)row * Dz;
    float* orow = out + (size_t)row * Dz;
    const int tid = threadIdx.x;
    float ss = 0.f;
    #pragma unroll
    for (int i = tid*4; i < Dz; i += 1024) {
        float4 v = *(const float4*)(xr + i);
        ss += v.x*v.x + v.y*v.y + v.z*v.z + v.w*v.w;
    }
    __shared__ float red[256];
    red[tid] = ss; __syncthreads();
    for (int s = 128; s > 0; s >>= 1) { if (tid < s) red[tid] += red[tid+s]; __syncthreads(); }
    const float scale = rsqrtf(red[0] / (float)Dz + 1e-6f);
    #pragma unroll
    for (int i = tid*4; i < Dz; i += 1024) {
        float4 v = *(const float4*)(xr + i);
        float4 ww = *(const float4*)(w + i);
        float4 o;
        o.x = v.x*scale*ww.x; o.y = v.y*scale*ww.y;
        o.z = v.z*scale*ww.z; o.w = v.w*scale*ww.w;
        *(float4*)(orow + i) = o;
    }
}

__global__ __launch_bounds__(256) void rope_kernel(float* __restrict__ q, float* __restrict__ k)
{
    const size_t idx = (size_t)blockIdx.x * 256 + threadIdx.x;
    if (idx >= (size_t)NTz * Hz * 64) return;
    const int    j    = (int)(idx & 63);
    const size_t th   = idx >> 6;
    const int    head = (int)(th & 15);
    const size_t tok  = th >> 4;
    const int    s    = (int)(tok & (Sz - 1));
    const double inv  = exp(-(double)(2*j) / 128.0 * 9.210340371976184);
    const double ang  = (double)s * inv;
    const float  c  = (float)cos(ang);
    const float  sn = (float)sin(ang);
    const size_t base = tok * (size_t)Dz + (size_t)head * DHz + j;
    float q1 = q[base], q2 = q[base + 64];
    q[base]      = q1*c - q2*sn;
    q[base + 64] = q2*c + q1*sn;
    float k1 = k[base], k2 = k[base + 64];
    k[base]      = k1*c - k2*sn;
    k[base + 64] = k2*c + k1*sn;
}

__global__ __launch_bounds__(256) void softmax_kernel(float* __restrict__ Sc, float* __restrict__ rowsum)
{
    const size_t row = blockIdx.x;
    float* p = Sc + row * (size_t)Sz;
    const int tid = threadIdx.x;
    float m = -1e30f;
    #pragma unroll
    for (int i = tid*4; i < Sz; i += 1024) {
        float4 v = *(const float4*)(p + i);
        m = fmaxf(m, fmaxf(fmaxf(v.x, v.y), fmaxf(v.z, v.w)));
    }
    __shared__ float red[256];
    red[tid] = m; __syncthreads();
    for (int s = 128; s > 0; s >>= 1) { if (tid < s) red[tid] = fmaxf(red[tid], red[tid+s]); __syncthreads(); }
    m = red[0];
    __syncthreads();
    float sum = 0.f;
    #pragma unroll
    for (int i = tid*4; i < Sz; i += 1024) {
        float4 v = *(const float4*)(p + i);
        v.x = expf(v.x - m); v.y = expf(v.y - m);
        v.z = expf(v.z - m); v.w = expf(v.w - m);
        sum += v.x + v.y + v.z + v.w;
        *(float4*)(p + i) = v;
    }
    red[tid] = sum; __syncthreads();
    for (int s = 128; s > 0; s >>= 1) { if (tid < s) red[tid] += red[tid+s]; __syncthreads(); }
    if (tid == 0) rowsum[row] = red[0];
}

__global__ __launch_bounds__(256) void router_kernel(
    const float* __restrict__ h, const float* __restrict__ rw,
    const float* __restrict__ rb, int* __restrict__ choice)
{
    const int t = blockIdx.x;
    const float* xr = h + (size_t)t * Dz;
    const int tid = threadIdx.x;
    float s0 = 0.f, s1 = 0.f;
    #pragma unroll
    for (int i = tid*4; i < Dz; i += 1024) {
        float4 v  = *(const float4*)(xr + i);
        float4 w0 = *(const float4*)(rw + i);
        float4 w1 = *(const float4*)(rw + Dz + i);
        s0 += v.x*w0.x + v.y*w0.y + v.z*w0.z + v.w*w0.w;
        s1 += v.x*w1.x + v.y*w1.y + v.z*w1.z + v.w*w1.w;
    }
    __shared__ float r0[256], r1[256];
    r0[tid] = s0; r1[tid] = s1; __syncthreads();
    for (int s = 128; s > 0; s >>= 1) {
        if (tid < s) { r0[tid] += r0[tid+s]; r1[tid] += r1[tid+s]; }
        __syncthreads();
    }
    if (tid == 0) {
        const float l0 = r0[0] + rb[0], l1 = r1[0] + rb[1];
        choice[t] = (l1 > l0) ? 1 : 0;
    }
}

__global__ __launch_bounds__(256) void act_kernel(
    float* __restrict__ gate, const float* __restrict__ up,
    const int* __restrict__ choice, int e)
{
    const int f = blockIdx.x * 256 + threadIdx.x;
    if (f >= Fz) return;
    const int tok = blockIdx.y;
    const size_t idx = (size_t)tok * Fz + f;
    if (choice[tok] == e) {
        const float g = gate[idx];
        gate[idx] = (g / (1.f + expf(-g))) * up[idx];
    } else {
        gate[idx] = 0.f;
    }
}

// ================= launch =================
extern "C" void kernel_launch(void* const* d_in, const int* in_sizes, int n_in,
                              void* d_out, int out_size)
{
    const float* x    = (const float*)d_in[0];
    const float* ln1w = (const float*)d_in[1];
    const float* wq   = (const float*)d_in[2];
    const float* bq   = (const float*)d_in[3];
    const float* wk   = (const float*)d_in[4];
    const float* bk   = (const float*)d_in[5];
    const float* wv   = (const float*)d_in[6];
    const float* bv   = (const float*)d_in[7];
    const float* wo   = (const float*)d_in[8];
    const float* ln2w = (const float*)d_in[9];
    const float* e1g  = (const float*)d_in[10];
    const float* e1u  = (const float*)d_in[11];
    const float* e1d  = (const float*)d_in[12];
    const float* e2g  = (const float*)d_in[13];
    const float* e2u  = (const float*)d_in[14];
    const float* e2d  = (const float*)d_in[15];
    const float* rw   = (const float*)d_in[16];
    const float* rb   = (const float*)d_in[17];
    float* out = (float*)d_out;

    float *h1, *q, *k, *v, *ctx, *h2, *sc, *rs, *gate, *up;
    int* choice;
    cudaGetSymbolAddress((void**)&h1,  g_h1);
    cudaGetSymbolAddress((void**)&q,   g_q);
    cudaGetSymbolAddress((void**)&k,   g_k);
    cudaGetSymbolAddress((void**)&v,   g_v);
    cudaGetSymbolAddress((void**)&ctx, g_ctx);
    cudaGetSymbolAddress((void**)&h2,  g_h2);
    cudaGetSymbolAddress((void**)&sc,  g_sc);
    cudaGetSymbolAddress((void**)&rs,  g_rs);
    cudaGetSymbolAddress((void**)&gate, g_gate);
    cudaGetSymbolAddress((void**)&up,   g_up);
    cudaGetSymbolAddress((void**)&choice, g_choice);

    const int SMEM_NT  = STAGE_NT  * 2 * 4;   // 73728 B
    const int SMEM_CTX = STAGE_CTX * 2 * 4;   // 70656 B
    cudaFuncSetAttribute(tf32_gemm_nt, cudaFuncAttributeMaxDynamicSharedMemorySize, SMEM_NT);
    cudaFuncSetAttribute(tf32_scores,  cudaFuncAttributeMaxDynamicSharedMemorySize, SMEM_NT);
    cudaFuncSetAttribute(tf32_ctx,     cudaFuncAttributeMaxDynamicSharedMemorySize, SMEM_CTX);

    // --- attention block ---
    rmsnorm_kernel<<<NTz, 256>>>(x, ln1w, h1);
    tf32_gemm_nt<<<dim3(Dz/128, NTz/128), 256, SMEM_NT>>>(h1, wq, q, bq, nullptr, NTz, Dz, Dz);
    tf32_gemm_nt<<<dim3(Dz/128, NTz/128), 256, SMEM_NT>>>(h1, wk, k, bk, nullptr, NTz, Dz, Dz);
    tf32_gemm_nt<<<dim3(Dz/128, NTz/128), 256, SMEM_NT>>>(h1, wv, v, bv, nullptr, NTz, Dz, Dz);
    rope_kernel<<<(NTz*Hz*64)/256, 256>>>(q, k);
    tf32_scores<<<dim3(Sz/128, Sz/128, BHz), 256, SMEM_NT>>>(q, k, sc);
    softmax_kernel<<<BHz*Sz, 256>>>(sc, rs);
    tf32_ctx<<<dim3(1, Sz/128, BHz), 256, SMEM_CTX>>>(sc, v, rs, ctx);
    tf32_gemm_nt<<<dim3(Dz/128, NTz/128), 256, SMEM_NT>>>(ctx, wo, h2, nullptr, x, NTz, Dz, Dz);

    // --- MoE block ---
    rmsnorm_kernel<<<NTz, 256>>>(h2, ln2w, h1);
    router_kernel<<<NTz, 256>>>(h1, rw, rb, choice);

    tf32_gemm_nt<<<dim3(Fz/128, NTz/128), 256, SMEM_NT>>>(h1, e1g, gate, nullptr, nullptr, NTz, Fz, Dz);
    tf32_gemm_nt<<<dim3(Fz/128, NTz/128), 256, SMEM_NT>>>(h1, e1u, up,   nullptr, nullptr, NTz, Fz, Dz);
    act_kernel<<<dim3((Fz+255)/256, NTz), 256>>>(gate, up, choice, 0);
    tf32_gemm_nt<<<dim3(Dz/128, NTz/128), 256, SMEM_NT>>>(gate, e1d, out, nullptr, h2, NTz, Dz, Fz);

    tf32_gemm_nt<<<dim3(Fz/128, NTz/128), 256, SMEM_NT>>>(h1, e2g, gate, nullptr, nullptr, NTz, Fz, Dz);
    tf32_gemm_nt<<<dim3(Fz/128, NTz/128), 256, SMEM_NT>>>(h1, e2u, up,   nullptr, nullptr, NTz, Fz, Dz);
    act_kernel<<<dim3((Fz+255)/256, NTz), 256>>>(gate, up, choice, 1);
    tf32_gemm_nt<<<dim3(Dz/128, NTz/128), 256, SMEM_NT>>>(gate, e2d, out, nullptr, out, NTz, Dz, Fz);
}